// round 1
// baseline (speedup 1.0000x reference)
#include <cuda_runtime.h>
#include <cuda_bf16.h>
#include <math.h>

// Problem constants (fixed shapes)
#define NNODES   16384
#define NEDGES   131072
#define NGRAPH   16
#define FEAT     120
#define L0C      32
#define L1C      16
#define L2C      8
#define NS       512
#define NB       256
#define KP       1344          // 1024 + 256 + 64
#define HID      1024

// -------- static device scratch (allocation-free rule) --------
__device__ float g_r[NEDGES];
__device__ float g_emb[(size_t)NEDGES * NB];
__device__ float g_h1[(size_t)NEDGES * HID];     // reused: distfilter hidden, then MLP hidden 1
__device__ float g_df[(size_t)NEDGES * NS];      // distfilter
__device__ float g_P[(size_t)NEDGES * KP];       // outer products
__device__ float g_mixed[(size_t)NEDGES * NS];   // mixed -> reg (in place)
__device__ float g_h2[(size_t)NEDGES * HID];
__device__ float g_Wcat[(size_t)KP * NS];

// ---------------- kernel 1: edge geometry -> r ----------------
__global__ void geom_kernel(const float* __restrict__ pos,
                            const float* __restrict__ cell,
                            const float* __restrict__ shift,
                            const int* __restrict__ ei,
                            const int* __restrict__ bvec) {
    int e = blockIdx.x * blockDim.x + threadIdx.x;
    if (e >= NEDGES) return;
    int src = ei[e];
    int dst = ei[NEDGES + e];
    int b = bvec[src];
    const float* C = cell + (size_t)b * 9;
    float s0 = shift[e * 3 + 0], s1 = shift[e * 3 + 1], s2 = shift[e * 3 + 2];
    // tvec[j] = sum_i shift[i] * cell[i][j]
    float t0 = s0 * C[0] + s1 * C[3] + s2 * C[6];
    float t1 = s0 * C[1] + s1 * C[4] + s2 * C[7];
    float t2 = s0 * C[2] + s1 * C[5] + s2 * C[8];
    float dx = pos[dst * 3 + 0] - pos[src * 3 + 0] + t0;
    float dy = pos[dst * 3 + 1] - pos[src * 3 + 1] + t1;
    float dz = pos[dst * 3 + 2] - pos[src * 3 + 2] + t2;
    float dist = sqrtf(dx * dx + dy * dy + dz * dz);
    g_r[e] = 1.0f / (dist + 1e-6f);
}

// ---------------- kernel 2: radial embedding ----------------
__global__ void emb_kernel() {
    int e = blockIdx.x;
    int n0 = threadIdx.x;   // 0..255
    float r = g_r[e];
    float amp = sqrtf(2.0f / 7.0f) / r;
    float k = 3.14159265358979323846f * r / 7.0f;
    g_emb[(size_t)e * NB + n0] = amp * sinf((float)(n0 + 1) * k);
}

// ---------------- kernel 3: build symmetrized Wcat ----------------
__global__ void wcat_kernel(const float* __restrict__ W0,
                            const float* __restrict__ W1,
                            const float* __restrict__ W2) {
    int idx = blockIdx.x * blockDim.x + threadIdx.x;
    const int total = KP * NS;
    if (idx >= total) return;
    int row = idx >> 9;   // / 512
    int w = idx & 511;
    float fan = sqrtf((float)(L0C * L0C + L1C * L1C + L2C * L2C));  // sqrt(1344)
    float v;
    if (row < 1024) {
        int u = row >> 5, vv = row & 31;
        v = (W0[(size_t)(u * 32 + vv) * NS + w] + W0[(size_t)(vv * 32 + u) * NS + w]) * (0.5f / fan);
    } else if (row < 1280) {
        int t = row - 1024;
        int u = t >> 4, vv = t & 15;
        v = (W1[(size_t)(u * 16 + vv) * NS + w] + W1[(size_t)(vv * 16 + u) * NS + w]) * (0.5f / (fan * sqrtf(3.0f)));
    } else {
        int t = row - 1280;
        int u = t >> 3, vv = t & 7;
        v = (W2[(size_t)(u * 8 + vv) * NS + w] + W2[(size_t)(vv * 8 + u) * NS + w]) * (0.5f / (fan * sqrtf(5.0f)));
    }
    g_Wcat[idx] = v;
}

// ---------------- kernel 4: outer products P ----------------
__global__ void pbuild_kernel(const float* __restrict__ nodes,
                              const int* __restrict__ ei) {
    int e = blockIdx.x;
    int tid = threadIdx.x;   // 128
    __shared__ float xs[FEAT];
    __shared__ float xd[FEAT];
    int src = ei[e];
    int dst = ei[NEDGES + e];
    if (tid < FEAT) {
        xs[tid] = nodes[(size_t)src * FEAT + tid];
        xd[tid] = nodes[(size_t)dst * FEAT + tid];
    }
    __syncthreads();
    float* Pe = g_P + (size_t)e * KP;
    #pragma unroll
    for (int it = 0; it < 11; it++) {
        int idx = tid + it * 128;
        if (idx >= KP) break;
        float v;
        if (idx < 1024) {
            int u = idx >> 5, w = idx & 31;
            v = xs[u] * xd[w];
        } else if (idx < 1280) {
            int t = idx - 1024;
            int u = t >> 4, w = t & 15;
            const float* a = xs + 32 + u * 3;
            const float* b = xd + 32 + w * 3;
            v = a[0] * b[0] + a[1] * b[1] + a[2] * b[2];
        } else {
            int t = idx - 1280;
            int u = t >> 3, w = t & 7;
            const float* a = xs + 80 + u * 5;
            const float* b = xd + 80 + w * 5;
            v = a[0] * b[0] + a[1] * b[1] + a[2] * b[2] + a[3] * b[3] + a[4] * b[4];
        }
        Pe[idx] = v;
    }
}

// ---------------- generic tiled SGEMM: C = epilogue(A @ B + bias) ----------------
// A: M x K row-major, B: K x N row-major, C: M x N row-major.
// BM=BN=128, BK=16, 256 threads, 8x8 per thread. All dims divisible.
template<bool BIAS, bool SILU>
__global__ __launch_bounds__(256, 2)
void sgemm_kernel(const float* __restrict__ A, const float* __restrict__ B,
                  const float* __restrict__ bias, float* __restrict__ C,
                  int M, int Nn, int K) {
    __shared__ float As[16][128];
    __shared__ float Bs[16][128];
    const int tid = threadIdx.x;
    const int tx = tid & 15;
    const int ty = tid >> 4;
    const int aRow0 = blockIdx.y * 128;
    const int bCol0 = blockIdx.x * 128;

    float acc[8][8];
    #pragma unroll
    for (int i = 0; i < 8; i++)
        #pragma unroll
        for (int j = 0; j < 8; j++) acc[i][j] = 0.0f;

    for (int k0 = 0; k0 < K; k0 += 16) {
        // load A tile (128x16) as float4, store transposed
        #pragma unroll
        for (int i = 0; i < 2; i++) {
            int idx = tid + i * 256;        // 0..511
            int m = idx >> 2;
            int kk4 = (idx & 3) << 2;
            float4 v = *(const float4*)(A + (size_t)(aRow0 + m) * K + k0 + kk4);
            As[kk4 + 0][m] = v.x;
            As[kk4 + 1][m] = v.y;
            As[kk4 + 2][m] = v.z;
            As[kk4 + 3][m] = v.w;
        }
        // load B tile (16x128)
        #pragma unroll
        for (int i = 0; i < 2; i++) {
            int idx = tid + i * 256;
            int kk = idx >> 5;
            int n4 = (idx & 31) << 2;
            *(float4*)(&Bs[kk][n4]) = *(const float4*)(B + (size_t)(k0 + kk) * Nn + bCol0 + n4);
        }
        __syncthreads();
        #pragma unroll
        for (int kk = 0; kk < 16; kk++) {
            float a[8], b[8];
            #pragma unroll
            for (int i = 0; i < 8; i++) a[i] = As[kk][ty * 8 + i];
            #pragma unroll
            for (int j = 0; j < 8; j++) b[j] = Bs[kk][tx * 8 + j];
            #pragma unroll
            for (int i = 0; i < 8; i++)
                #pragma unroll
                for (int j = 0; j < 8; j++)
                    acc[i][j] = fmaf(a[i], b[j], acc[i][j]);
        }
        __syncthreads();
    }
    // epilogue
    #pragma unroll
    for (int i = 0; i < 8; i++) {
        int m = aRow0 + ty * 8 + i;
        #pragma unroll
        for (int j = 0; j < 8; j += 4) {
            int n = bCol0 + tx * 8 + j;
            float4 v;
            float* pv = &v.x;
            #pragma unroll
            for (int q = 0; q < 4; q++) {
                float x = acc[i][j + q];
                if (BIAS) x += bias[n + q];
                if (SILU) x = x / (1.0f + expf(-x));
                pv[q] = x;
            }
            *(float4*)(C + (size_t)m * Nn + n) = v;
        }
    }
}

// ---------------- kernel: LayerNorm(mixed) * distfilter, in place ----------------
__global__ void ln_mult_kernel(const float* __restrict__ ln_g,
                               const float* __restrict__ ln_b) {
    int e = blockIdx.x;
    int tid = threadIdx.x;   // 128 threads, 4 floats each
    __shared__ float sh[4];
    float* row = g_mixed + (size_t)e * NS;
    float4 x = *(const float4*)(row + tid * 4);
    float s = x.x + x.y + x.z + x.w;
    int lane = tid & 31, wid = tid >> 5;
    #pragma unroll
    for (int o = 16; o; o >>= 1) s += __shfl_xor_sync(0xffffffffu, s, o);
    if (!lane) sh[wid] = s;
    __syncthreads();
    float mu = (sh[0] + sh[1] + sh[2] + sh[3]) * (1.0f / 512.0f);
    float d0 = x.x - mu, d1 = x.y - mu, d2 = x.z - mu, d3 = x.w - mu;
    float s2 = d0 * d0 + d1 * d1 + d2 * d2 + d3 * d3;
    #pragma unroll
    for (int o = 16; o; o >>= 1) s2 += __shfl_xor_sync(0xffffffffu, s2, o);
    __syncthreads();
    if (!lane) sh[wid] = s2;
    __syncthreads();
    float var = (sh[0] + sh[1] + sh[2] + sh[3]) * (1.0f / 512.0f);
    float inv = rsqrtf(var + 1e-5f);
    float4 df = *(const float4*)(g_df + (size_t)e * NS + tid * 4);
    float4 gg = *(const float4*)(ln_g + tid * 4);
    float4 bb = *(const float4*)(ln_b + tid * 4);
    float4 y;
    y.x = (d0 * inv * gg.x + bb.x) * df.x;
    y.y = (d1 * inv * gg.y + bb.y) * df.y;
    y.z = (d2 * inv * gg.z + bb.z) * df.z;
    y.w = (d3 * inv * gg.w + bb.w) * df.w;
    *(float4*)(row + tid * 4) = y;
}

// ---------------- final GEMV: out = h2 @ mo_w + mo_b ----------------
__global__ void gemv_kernel(const float* __restrict__ w,
                            const float* __restrict__ b,
                            float* __restrict__ out) {
    int gwarp = (blockIdx.x * blockDim.x + threadIdx.x) >> 5;
    int lane = threadIdx.x & 31;
    if (gwarp >= NEDGES) return;
    const float4* h4 = (const float4*)(g_h2 + (size_t)gwarp * HID);
    const float4* w4 = (const float4*)w;
    float s = 0.0f;
    #pragma unroll
    for (int i = 0; i < 8; i++) {
        float4 a = h4[lane + i * 32];
        float4 ww = w4[lane + i * 32];
        s += a.x * ww.x + a.y * ww.y + a.z * ww.z + a.w * ww.w;
    }
    #pragma unroll
    for (int o = 16; o; o >>= 1) s += __shfl_xor_sync(0xffffffffu, s, o);
    if (!lane) out[gwarp] = s + b[0];
}

// ---------------- host launcher ----------------
extern "C" void kernel_launch(void* const* d_in, const int* in_sizes, int n_in,
                              void* d_out, int out_size) {
    const float* nodes     = (const float*)d_in[0];
    const float* pos       = (const float*)d_in[1];
    const float* cell      = (const float*)d_in[2];
    const float* eshift    = (const float*)d_in[3];
    const float* W0        = (const float*)d_in[4];
    const float* W1        = (const float*)d_in[5];
    const float* W2        = (const float*)d_in[6];
    const float* ln_g      = (const float*)d_in[7];
    const float* ln_b      = (const float*)d_in[8];
    const float* df_w1     = (const float*)d_in[9];
    const float* df_b1     = (const float*)d_in[10];
    const float* df_w2     = (const float*)d_in[11];
    const float* df_b2     = (const float*)d_in[12];
    const float* mi_w1     = (const float*)d_in[13];
    const float* mi_b1     = (const float*)d_in[14];
    const float* mi_w2     = (const float*)d_in[15];
    const float* mi_b2     = (const float*)d_in[16];
    const float* mo_w      = (const float*)d_in[17];
    const float* mo_b      = (const float*)d_in[18];
    const int*   edge_index = (const int*)d_in[19];
    const int*   batch_vec  = (const int*)d_in[20];
    float* out = (float*)d_out;

    float *pEmb, *pH1, *pDf, *pP, *pMix, *pH2, *pW;
    cudaGetSymbolAddress((void**)&pEmb, g_emb);
    cudaGetSymbolAddress((void**)&pH1,  g_h1);
    cudaGetSymbolAddress((void**)&pDf,  g_df);
    cudaGetSymbolAddress((void**)&pP,   g_P);
    cudaGetSymbolAddress((void**)&pMix, g_mixed);
    cudaGetSymbolAddress((void**)&pH2,  g_h2);
    cudaGetSymbolAddress((void**)&pW,   g_Wcat);

    // 1. geometry -> r
    geom_kernel<<<(NEDGES + 255) / 256, 256>>>(pos, cell, eshift, edge_index, batch_vec);
    // 2. radial embedding
    emb_kernel<<<NEDGES, NB>>>();
    // 3. symmetrized concat weight
    wcat_kernel<<<(KP * NS + 255) / 256, 256>>>(W0, W1, W2);
    // 4. outer products
    pbuild_kernel<<<NEDGES, 128>>>(nodes, edge_index);
    // 5. distfilter MLP: silu(emb @ df_w1 + b1) @ df_w2 + b2
    sgemm_kernel<true, true><<<dim3(HID / 128, NEDGES / 128), 256>>>(pEmb, df_w1, df_b1, pH1, NEDGES, HID, NB);
    sgemm_kernel<true, false><<<dim3(NS / 128, NEDGES / 128), 256>>>(pH1, df_w2, df_b2, pDf, NEDGES, NS, HID);
    // 6. mixed = P @ Wcat
    sgemm_kernel<false, false><<<dim3(NS / 128, NEDGES / 128), 256>>>(pP, pW, nullptr, pMix, NEDGES, NS, KP);
    // 7. LayerNorm * distfilter (in place into g_mixed)
    ln_mult_kernel<<<NEDGES, 128>>>(ln_g, ln_b);
    // 8. MLP: silu(reg @ mi_w1 + b), silu(h @ mi_w2 + b)
    sgemm_kernel<true, true><<<dim3(HID / 128, NEDGES / 128), 256>>>(pMix, mi_w1, mi_b1, pH1, NEDGES, HID, NS);
    sgemm_kernel<true, true><<<dim3(HID / 128, NEDGES / 128), 256>>>(pH1, mi_w2, mi_b2, pH2, NEDGES, HID, HID);
    // 9. output head
    gemv_kernel<<<(NEDGES * 32 + 255) / 256, 256>>>(mo_w, mo_b, out);
}

// round 3
// speedup vs baseline: 2.1110x; 2.1110x over previous
#include <cuda_runtime.h>
#include <cuda_fp16.h>
#include <math.h>
#include <stdint.h>

#define NEDGES 131072
#define FEAT   120
#define NS     512
#define KP     1344
#define MBLK   1024      // NEDGES/128

// -------- static device scratch (allocation-free rule) --------
__device__ float  g_r[NEDGES];
__device__ __half g_embhl[(size_t)NEDGES * 512];    // [E][hi256|lo256]
__device__ __half g_h1hl [(size_t)NEDGES * 2048];   // [E][hi1024|lo1024] (reused)
__device__ float  g_df   [(size_t)NEDGES * NS];
__device__ __half g_Phl  [(size_t)NEDGES * 2688];   // [E][hi1344|lo1344]
__device__ float  g_mixed[(size_t)NEDGES * NS];
__device__ __half g_reghl[(size_t)NEDGES * 1024];   // [E][hi512|lo512]
// transposed hi/lo weights: [N rows][hiK|loK]
__device__ __half g_WcatT[(size_t)512  * 2688];
__device__ __half g_df1T [(size_t)1024 * 512];
__device__ __half g_df2T [(size_t)512  * 2048];
__device__ __half g_mi1T [(size_t)1024 * 1024];
__device__ __half g_mi2T [(size_t)1024 * 2048];

__device__ __forceinline__ void split_h(float x, __half& h, __half& l) {
    h = __float2half_rn(x);
    l = __float2half_rn(x - __half2float(h));
}
__device__ __forceinline__ uint32_t smem_u32(const void* p) {
    uint32_t a;
    asm("{ .reg .u64 t; cvta.to.shared.u64 t, %1; cvt.u32.u64 %0, t; }" : "=r"(a) : "l"(p));
    return a;
}
__device__ __forceinline__ void cp16(uint32_t s, const void* g) {
    asm volatile("cp.async.cg.shared.global [%0], [%1], 16;" :: "r"(s), "l"(g) : "memory");
}
__device__ __forceinline__ void ldm4(uint32_t* r, uint32_t addr) {
    asm volatile("ldmatrix.sync.aligned.m8n8.x4.shared.b16 {%0,%1,%2,%3}, [%4];"
                 : "=r"(r[0]), "=r"(r[1]), "=r"(r[2]), "=r"(r[3]) : "r"(addr));
}
__device__ __forceinline__ void mma16816(float* c, const uint32_t* a, uint32_t b0, uint32_t b1) {
    asm volatile("mma.sync.aligned.m16n8k16.row.col.f32.f16.f16.f32 "
                 "{%0,%1,%2,%3}, {%4,%5,%6,%7}, {%8,%9}, {%0,%1,%2,%3};"
                 : "+f"(c[0]), "+f"(c[1]), "+f"(c[2]), "+f"(c[3])
                 : "r"(a[0]), "r"(a[1]), "r"(a[2]), "r"(a[3]), "r"(b0), "r"(b1));
}

// ---------------- kernel: edge geometry -> r ----------------
__global__ void geom_kernel(const float* __restrict__ pos,
                            const float* __restrict__ cell,
                            const float* __restrict__ shift,
                            const int* __restrict__ ei,
                            const int* __restrict__ bvec) {
    int e = blockIdx.x * blockDim.x + threadIdx.x;
    if (e >= NEDGES) return;
    int src = ei[e];
    int dst = ei[NEDGES + e];
    int b = bvec[src];
    const float* C = cell + (size_t)b * 9;
    float s0 = shift[e * 3 + 0], s1 = shift[e * 3 + 1], s2 = shift[e * 3 + 2];
    float t0 = s0 * C[0] + s1 * C[3] + s2 * C[6];
    float t1 = s0 * C[1] + s1 * C[4] + s2 * C[7];
    float t2 = s0 * C[2] + s1 * C[5] + s2 * C[8];
    float dx = pos[dst * 3 + 0] - pos[src * 3 + 0] + t0;
    float dy = pos[dst * 3 + 1] - pos[src * 3 + 1] + t1;
    float dz = pos[dst * 3 + 2] - pos[src * 3 + 2] + t2;
    float dist = sqrtf(dx * dx + dy * dy + dz * dz);
    g_r[e] = 1.0f / (dist + 1e-6f);
}

// ---------------- radial embedding (hi/lo fp16) ----------------
__global__ void emb_kernel() {
    int e = blockIdx.x;
    int k = threadIdx.x;   // 0..255
    float r = g_r[e];
    float amp = sqrtf(2.0f / 7.0f) / r;
    float ph = 3.14159265358979323846f * r / 7.0f;
    float x = amp * sinf((float)(k + 1) * ph);
    __half h, l; split_h(x, h, l);
    g_embhl[(size_t)e * 512 + k] = h;
    g_embhl[(size_t)e * 512 + 256 + k] = l;
}

// ---------------- symmetrized Wcat, transposed hi/lo ----------------
__global__ void wcat_kernel(const float* __restrict__ W0,
                            const float* __restrict__ W1,
                            const float* __restrict__ W2) {
    int idx = blockIdx.x * blockDim.x + threadIdx.x;
    if (idx >= KP * NS) return;
    int k = idx >> 9;
    int n = idx & 511;
    float fan = sqrtf(1344.0f);
    float v;
    if (k < 1024) {
        int u = k >> 5, vv = k & 31;
        v = (W0[(size_t)(u * 32 + vv) * NS + n] + W0[(size_t)(vv * 32 + u) * NS + n]) * (0.5f / fan);
    } else if (k < 1280) {
        int t = k - 1024;
        int u = t >> 4, vv = t & 15;
        v = (W1[(size_t)(u * 16 + vv) * NS + n] + W1[(size_t)(vv * 16 + u) * NS + n]) * (0.5f / (fan * sqrtf(3.0f)));
    } else {
        int t = k - 1280;
        int u = t >> 3, vv = t & 7;
        v = (W2[(size_t)(u * 8 + vv) * NS + n] + W2[(size_t)(vv * 8 + u) * NS + n]) * (0.5f / (fan * sqrtf(5.0f)));
    }
    __half h, l; split_h(v, h, l);
    g_WcatT[(size_t)n * 2688 + k] = h;
    g_WcatT[(size_t)n * 2688 + 1344 + k] = l;
}

// ---------------- weight transpose+split: W[K x N] -> out[N][hiK|loK] ----------------
__global__ void wt_convert(const float* __restrict__ W, __half* __restrict__ out,
                           int K, int N) {
    int idx = blockIdx.x * blockDim.x + threadIdx.x;
    if (idx >= K * N) return;
    int n = idx / K, k = idx - n * K;
    float v = W[(size_t)k * N + n];
    __half h, l; split_h(v, h, l);
    out[(size_t)n * 2 * K + k] = h;
    out[(size_t)n * 2 * K + K + k] = l;
}

// ---------------- outer products P (hi/lo fp16) ----------------
__global__ void pbuild_kernel(const float* __restrict__ nodes,
                              const int* __restrict__ ei) {
    int e = blockIdx.x;
    int tid = threadIdx.x;   // 128
    __shared__ float xs[FEAT];
    __shared__ float xd[FEAT];
    int src = ei[e];
    int dst = ei[NEDGES + e];
    if (tid < FEAT) {
        xs[tid] = nodes[(size_t)src * FEAT + tid];
        xd[tid] = nodes[(size_t)dst * FEAT + tid];
    }
    __syncthreads();
    __half* Pe = g_Phl + (size_t)e * 2688;
    #pragma unroll
    for (int it = 0; it < 11; it++) {
        int idx = tid + it * 128;
        if (idx >= KP) break;
        float v;
        if (idx < 1024) {
            int u = idx >> 5, w = idx & 31;
            v = xs[u] * xd[w];
        } else if (idx < 1280) {
            int t = idx - 1024;
            int u = t >> 4, w = t & 15;
            const float* a = xs + 32 + u * 3;
            const float* b = xd + 32 + w * 3;
            v = a[0] * b[0] + a[1] * b[1] + a[2] * b[2];
        } else {
            int t = idx - 1280;
            int u = t >> 3, w = t & 7;
            const float* a = xs + 80 + u * 5;
            const float* b = xd + 80 + w * 5;
            v = a[0] * b[0] + a[1] * b[1] + a[2] * b[2] + a[3] * b[3] + a[4] * b[4];
        }
        __half h, l; split_h(v, h, l);
        Pe[idx] = h;
        Pe[1344 + idx] = l;
    }
}

// ======================= HMMA GEMM =======================
// C[M x Ntot] = epi( sum over 3 split-products of A(M x K') @ B^T(Ntot x K') )
// A global [M][hiK|loK], B global [N][hiK|loK].  K' = 3K via segment remap:
//   seg0: Ah*Bh   seg1: Ah*Bl   seg2: Al*Bh
// CTA tile 128x128, BK=32, 3-stage cp.async, 8 warps (warp tile 64x32).
// MODE: 0 = fp32 out, 1 = fp16 hi/lo planes out, 2 = fused head (dot with wv -> atomicAdd)
template<int MODE, bool BIAS, bool SILU>
__global__ __launch_bounds__(256, 2)
void hgemm(const __half* __restrict__ A, const __half* __restrict__ B,
           const float* __restrict__ bias, const float* __restrict__ wv,
           float* __restrict__ outF, __half* __restrict__ outHL,
           int K, int Ntot) {
    __shared__ __align__(16) char smem[49152];   // 3x8KB A | 3x8KB B ; reused as epilogue slab
    const uint32_t sbase = smem_u32(smem);
    const int tid = threadIdx.x;
    const int lane = tid & 31;
    const int wid = tid >> 5;
    const int wm = wid & 1;        // 2 warps along M
    const int wn = wid >> 1;       // 4 warps along N
    const int m0 = blockIdx.y << 7;
    const int n0 = blockIdx.x << 7;
    const int A2K = 2 * K;
    const size_t strB = (size_t)A2K * sizeof(__half);   // bytes per row
    const int nch = (3 * K) >> 5;

    float acc[4][4][4];
    #pragma unroll
    for (int i = 0; i < 4; i++)
        #pragma unroll
        for (int j = 0; j < 4; j++)
            #pragma unroll
            for (int q = 0; q < 4; q++) acc[i][j][q] = 0.0f;

    auto load_chunk = [&](int s, int c) {
        int kg = c << 5;
        int seg = kg / K;
        int kin = kg - seg * K;
        int acol = kin + (seg == 2 ? K : 0);
        int bcol = kin + (seg == 1 ? K : 0);
        const char* Ag = (const char*)(A + (size_t)m0 * A2K + acol);
        const char* Bg = (const char*)(B + (size_t)n0 * A2K + bcol);
        #pragma unroll
        for (int i = 0; i < 2; i++) {
            int idx = tid + (i << 8);      // 0..511
            int row = idx >> 2;
            int ch = idx & 3;
            uint32_t sw = (uint32_t)((ch ^ ((row >> 1) & 3)) << 4);
            cp16(sbase + (uint32_t)(s * 8192 + row * 64) + sw, Ag + (size_t)row * strB + ch * 16);
            cp16(sbase + 24576u + (uint32_t)(s * 8192 + row * 64) + sw, Bg + (size_t)row * strB + ch * 16);
        }
    };

    auto compute = [&](int s) {
        const uint32_t sA = sbase + (uint32_t)(s * 8192);
        const uint32_t sB = sbase + 24576u + (uint32_t)(s * 8192);
        #pragma unroll
        for (int kk = 0; kk < 2; kk++) {
            uint32_t a[4][4];
            #pragma unroll
            for (int mi = 0; mi < 4; mi++) {
                int r = wm * 64 + mi * 16 + (lane & 15);
                int ch = 2 * kk + (lane >> 4);
                ldm4(a[mi], sA + (uint32_t)(r * 64 + ((ch ^ ((r >> 1) & 3)) << 4)));
            }
            uint32_t b[2][4];
            #pragma unroll
            for (int nh = 0; nh < 2; nh++) {
                int r = wn * 32 + nh * 16 + (lane & 15);
                int ch = 2 * kk + (lane >> 4);
                ldm4(b[nh], sB + (uint32_t)(r * 64 + ((ch ^ ((r >> 1) & 3)) << 4)));
            }
            #pragma unroll
            for (int mi = 0; mi < 4; mi++)
                #pragma unroll
                for (int ni = 0; ni < 4; ni++)
                    mma16816(acc[mi][ni], a[mi], b[ni >> 1][ni & 1], b[ni >> 1][(ni & 1) + 2]);
        }
    };

    load_chunk(0, 0);
    asm volatile("cp.async.commit_group;" ::: "memory");
    load_chunk(1, 1);
    asm volatile("cp.async.commit_group;" ::: "memory");

    for (int c = 0; c < nch; c++) {
        asm volatile("cp.async.wait_group 1;" ::: "memory");
        __syncthreads();
        if (c + 2 < nch) load_chunk((c + 2) % 3, c + 2);
        asm volatile("cp.async.commit_group;" ::: "memory");
        compute(c % 3);
    }
    asm volatile("cp.async.wait_group 0;" ::: "memory");
    __syncthreads();

    // ---------------- epilogue through SMEM slab (128 x 72 fp32) ----------------
    float* slab = (float*)smem;
    const int nl = tid & 63;          // column within 64-col pass
    const int rg = tid >> 6;          // row group 0..3 (32 rows each)
    #pragma unroll
    for (int p = 0; p < 2; p++) {
        if ((wn >> 1) == p) {
            #pragma unroll
            for (int mi = 0; mi < 4; mi++) {
                int r = wm * 64 + mi * 16 + (lane >> 2);
                #pragma unroll
                for (int ni = 0; ni < 4; ni++) {
                    int lc = (wn & 1) * 32 + ni * 8 + (lane & 3) * 2;
                    *(float2*)&slab[r * 72 + lc] = make_float2(acc[mi][ni][0], acc[mi][ni][1]);
                    *(float2*)&slab[(r + 8) * 72 + lc] = make_float2(acc[mi][ni][2], acc[mi][ni][3]);
                }
            }
        }
        __syncthreads();
        int n = n0 + p * 64 + nl;
        float bi = BIAS ? bias[n] : 0.0f;
        float wr = (MODE == 2) ? wv[n] : 0.0f;
        #pragma unroll
        for (int rr = 0; rr < 32; rr++) {
            int row = rg * 32 + rr;
            float x = slab[row * 72 + nl];
            if (BIAS) x += bi;
            if (SILU) x = x / (1.0f + __expf(-x));
            size_t gm = (size_t)(m0 + row);
            if (MODE == 0) {
                outF[gm * Ntot + n] = x;
            } else if (MODE == 1) {
                __half h = __float2half_rn(x);
                __half l = __float2half_rn(x - __half2float(h));
                outHL[gm * (size_t)(2 * Ntot) + n] = h;
                outHL[gm * (size_t)(2 * Ntot) + Ntot + n] = l;
            } else {
                float v = x * wr;
                #pragma unroll
                for (int o = 16; o; o >>= 1) v += __shfl_xor_sync(0xffffffffu, v, o);
                if (lane == 0) atomicAdd(outF + gm, v);
            }
        }
        __syncthreads();
    }
}

// ---------------- LayerNorm(mixed) * distfilter -> reg (hi/lo fp16) ----------------
__global__ void ln_mult_kernel(const float* __restrict__ ln_g,
                               const float* __restrict__ ln_b) {
    int e = blockIdx.x;
    int tid = threadIdx.x;   // 128 threads, 4 floats each
    __shared__ float sh[4];
    const float* row = g_mixed + (size_t)e * NS;
    float4 x = *(const float4*)(row + tid * 4);
    float s = x.x + x.y + x.z + x.w;
    int lane = tid & 31, wid = tid >> 5;
    #pragma unroll
    for (int o = 16; o; o >>= 1) s += __shfl_xor_sync(0xffffffffu, s, o);
    if (!lane) sh[wid] = s;
    __syncthreads();
    float mu = (sh[0] + sh[1] + sh[2] + sh[3]) * (1.0f / 512.0f);
    float d0 = x.x - mu, d1 = x.y - mu, d2 = x.z - mu, d3 = x.w - mu;
    float s2 = d0 * d0 + d1 * d1 + d2 * d2 + d3 * d3;
    #pragma unroll
    for (int o = 16; o; o >>= 1) s2 += __shfl_xor_sync(0xffffffffu, s2, o);
    __syncthreads();
    if (!lane) sh[wid] = s2;
    __syncthreads();
    float var = (sh[0] + sh[1] + sh[2] + sh[3]) * (1.0f / 512.0f);
    float inv = rsqrtf(var + 1e-5f);
    float4 df = *(const float4*)(g_df + (size_t)e * NS + tid * 4);
    float4 gg = *(const float4*)(ln_g + tid * 4);
    float4 bb = *(const float4*)(ln_b + tid * 4);
    float y0 = (d0 * inv * gg.x + bb.x) * df.x;
    float y1 = (d1 * inv * gg.y + bb.y) * df.y;
    float y2 = (d2 * inv * gg.z + bb.z) * df.z;
    float y3 = (d3 * inv * gg.w + bb.w) * df.w;
    __half* o = g_reghl + (size_t)e * 1024 + tid * 4;
    __half h, l;
    split_h(y0, h, l); o[0] = h; o[512] = l;
    split_h(y1, h, l); o[1] = h; o[513] = l;
    split_h(y2, h, l); o[2] = h; o[514] = l;
    split_h(y3, h, l); o[3] = h; o[515] = l;
}

// ---------------- init output with bias ----------------
__global__ void init_out(float* __restrict__ out, const float* __restrict__ b) {
    int i = blockIdx.x * blockDim.x + threadIdx.x;
    if (i < NEDGES) out[i] = b[0];
}

// ---------------- host launcher ----------------
extern "C" void kernel_launch(void* const* d_in, const int* in_sizes, int n_in,
                              void* d_out, int out_size) {
    const float* nodes  = (const float*)d_in[0];
    const float* pos    = (const float*)d_in[1];
    const float* cell   = (const float*)d_in[2];
    const float* eshift = (const float*)d_in[3];
    const float* W0     = (const float*)d_in[4];
    const float* W1     = (const float*)d_in[5];
    const float* W2     = (const float*)d_in[6];
    const float* ln_g   = (const float*)d_in[7];
    const float* ln_b   = (const float*)d_in[8];
    const float* df_w1  = (const float*)d_in[9];
    const float* df_b1  = (const float*)d_in[10];
    const float* df_w2  = (const float*)d_in[11];
    const float* df_b2  = (const float*)d_in[12];
    const float* mi_w1  = (const float*)d_in[13];
    const float* mi_b1  = (const float*)d_in[14];
    const float* mi_w2  = (const float*)d_in[15];
    const float* mi_b2  = (const float*)d_in[16];
    const float* mo_w   = (const float*)d_in[17];
    const float* mo_b   = (const float*)d_in[18];
    const int* edge_index = (const int*)d_in[19];
    const int* batch_vec  = (const int*)d_in[20];
    float* out = (float*)d_out;

    __half *pEmb, *pH1, *pP, *pReg, *pWcat, *pDf1, *pDf2, *pMi1, *pMi2;
    float *pDf, *pMix;
    cudaGetSymbolAddress((void**)&pEmb,  g_embhl);
    cudaGetSymbolAddress((void**)&pH1,   g_h1hl);
    cudaGetSymbolAddress((void**)&pP,    g_Phl);
    cudaGetSymbolAddress((void**)&pReg,  g_reghl);
    cudaGetSymbolAddress((void**)&pWcat, g_WcatT);
    cudaGetSymbolAddress((void**)&pDf1,  g_df1T);
    cudaGetSymbolAddress((void**)&pDf2,  g_df2T);
    cudaGetSymbolAddress((void**)&pMi1,  g_mi1T);
    cudaGetSymbolAddress((void**)&pMi2,  g_mi2T);
    cudaGetSymbolAddress((void**)&pDf,   g_df);
    cudaGetSymbolAddress((void**)&pMix,  g_mixed);

    // prep
    geom_kernel<<<(NEDGES + 255) / 256, 256>>>(pos, cell, eshift, edge_index, batch_vec);
    emb_kernel<<<NEDGES, 256>>>();
    wcat_kernel<<<(KP * NS + 255) / 256, 256>>>(W0, W1, W2);
    pbuild_kernel<<<NEDGES, 128>>>(nodes, edge_index);
    wt_convert<<<(256 * 1024 + 255) / 256, 256>>>(df_w1, pDf1, 256, 1024);
    wt_convert<<<(1024 * 512 + 255) / 256, 256>>>(df_w2, pDf2, 1024, 512);
    wt_convert<<<(512 * 1024 + 255) / 256, 256>>>(mi_w1, pMi1, 512, 1024);
    wt_convert<<<(1024 * 1024 + 255) / 256, 256>>>(mi_w2, pMi2, 1024, 1024);
    init_out<<<(NEDGES + 255) / 256, 256>>>(out, mo_b);

    // G1: h1 = silu(emb @ df_w1 + b1)   [E x 1024] -> hi/lo planes
    hgemm<1, true, true><<<dim3(8, MBLK), 256>>>(pEmb, pDf1, df_b1, nullptr, nullptr, pH1, 256, 1024);
    // G2: df = h1 @ df_w2 + b2          [E x 512] fp32
    hgemm<0, true, false><<<dim3(4, MBLK), 256>>>(pH1, pDf2, df_b2, nullptr, pDf, nullptr, 1024, 512);
    // G3: mixed = P @ Wcat              [E x 512] fp32
    hgemm<0, false, false><<<dim3(4, MBLK), 256>>>(pP, pWcat, nullptr, nullptr, pMix, nullptr, 1344, 512);
    // LN * distfilter -> reg (hi/lo)
    ln_mult_kernel<<<NEDGES, 128>>>(ln_g, ln_b);
    // G4: h = silu(reg @ mi_w1 + b)     [E x 1024] -> hi/lo planes (reuse g_h1hl)
    hgemm<1, true, true><<<dim3(8, MBLK), 256>>>(pReg, pMi1, mi_b1, nullptr, nullptr, pH1, 512, 1024);
    // G5: out += silu(h @ mi_w2 + b) . mo_w   (fused head)
    hgemm<2, true, true><<<dim3(8, MBLK), 256>>>(pH1, pMi2, mi_b2, mo_w, out, nullptr, 1024, 1024);
}